// round 1
// baseline (speedup 1.0000x reference)
#include <cuda_runtime.h>
#include <cuda_bf16.h>

// Shapes (fixed by the problem):
//   X[131072,256], W1[256,384], b1[384], W2[384,64], b2[64],
//   phi[5,64] int32, pi[5,64,16], out[131072,16]
#define NF  256
#define NH  384
#define NL  64
#define NO  16
#define NE  5

// Scratch for h = sigmoid(X@W1+b1): 131072*384 floats (~201 MB), static device mem.
__device__ float g_h[131072UL * 384UL];

__device__ __forceinline__ float fsigmoid(float v) {
    return 1.0f / (1.0f + __expf(-v));
}

// ---------------------------------------------------------------------------
// Kernel 1: h = sigmoid(X @ W1 + b1)
// Classic smem-tiled SGEMM: BM=128, BN=128, BK=16, 8x8 microtile, 256 threads.
// Grid: (NH/128, N/128)
// ---------------------------------------------------------------------------
#define BM 128
#define BN 128
#define BK 16
#define TM 8
#define TN 8

__global__ __launch_bounds__(256)
void gemm1_sigmoid(const float* __restrict__ X, const float* __restrict__ W1,
                   const float* __restrict__ b1) {
    __shared__ float As[BK][BM];   // transposed A tile
    __shared__ float Bs[BK][BN];

    const int bx = blockIdx.x;          // column tile (0..2)
    const int by = blockIdx.y;          // row tile
    const int tid = threadIdx.x;
    const int tcol = tid % (BN / TN);   // 0..15
    const int trow = tid / (BN / TN);   // 0..15

    float acc[TM][TN];
#pragma unroll
    for (int i = 0; i < TM; i++)
#pragma unroll
        for (int j = 0; j < TN; j++) acc[i][j] = 0.0f;

    const float* Ab = X + (size_t)by * BM * NF;
    const float* Bb = W1 + bx * BN;

    const int aRow = tid / 4;            // 0..63
    const int aCol = (tid % 4) * 4;      // 0,4,8,12
    const int bRow = tid / 32;           // 0..7
    const int bCol = (tid % 32) * 4;

    for (int k0 = 0; k0 < NF; k0 += BK) {
#pragma unroll
        for (int p = 0; p < 2; p++) {
            float4 v = *(const float4*)(Ab + (size_t)(aRow + 64 * p) * NF + k0 + aCol);
            As[aCol + 0][aRow + 64 * p] = v.x;
            As[aCol + 1][aRow + 64 * p] = v.y;
            As[aCol + 2][aRow + 64 * p] = v.z;
            As[aCol + 3][aRow + 64 * p] = v.w;
        }
#pragma unroll
        for (int p = 0; p < 2; p++) {
            float4 v = *(const float4*)(Bb + (size_t)(k0 + bRow + 8 * p) * NH + bCol);
            *(float4*)&Bs[bRow + 8 * p][bCol] = v;
        }
        __syncthreads();

#pragma unroll
        for (int kk = 0; kk < BK; kk++) {
            float a[TM], b[TN];
            float4 a0 = *(const float4*)&As[kk][trow * TM];
            float4 a1 = *(const float4*)&As[kk][trow * TM + 4];
            a[0]=a0.x; a[1]=a0.y; a[2]=a0.z; a[3]=a0.w;
            a[4]=a1.x; a[5]=a1.y; a[6]=a1.z; a[7]=a1.w;
            float4 b0 = *(const float4*)&Bs[kk][tcol * TN];
            float4 b1v= *(const float4*)&Bs[kk][tcol * TN + 4];
            b[0]=b0.x; b[1]=b0.y; b[2]=b0.z; b[3]=b0.w;
            b[4]=b1v.x;b[5]=b1v.y;b[6]=b1v.z;b[7]=b1v.w;
#pragma unroll
            for (int i = 0; i < TM; i++)
#pragma unroll
                for (int j = 0; j < TN; j++)
                    acc[i][j] = fmaf(a[i], b[j], acc[i][j]);
        }
        __syncthreads();
    }

    // Epilogue: add bias, sigmoid, store to g_h
#pragma unroll
    for (int i = 0; i < TM; i++) {
        size_t row = (size_t)by * BM + trow * TM + i;
#pragma unroll
        for (int j = 0; j < TN; j++) {
            int col = bx * BN + tcol * TN + j;
            float v = acc[i][j] + b1[col];
            g_h[row * NH + col] = fsigmoid(v);
        }
    }
}

// ---------------------------------------------------------------------------
// Kernel 2: latent = sigmoid(h @ W2 + b2); soft tree routing; out = mu @ pi / E
// One CTA per 64 rows. 256 threads.
//   GEMM phase: 64x64x384, 4x4 microtile per thread (16x16 thread grid).
//   Tree phase: 4 threads per row, each owns 4 of the 16 outputs.
// ---------------------------------------------------------------------------
__global__ __launch_bounds__(256)
void fused2(const float* __restrict__ W2, const float* __restrict__ b2,
            const int* __restrict__ phi, const float* __restrict__ pi,
            float* __restrict__ out) {
    __shared__ float hs[16 * 64];        // transposed h tile  [k][row]
    __shared__ float w2s[16 * 64];       // W2 tile            [k][col]
    __shared__ float lat[64 * 65];       // latent, padded row stride 65
    __shared__ float pis[NE * NL * NO];  // 5120
    __shared__ float b2s[NL];
    __shared__ int   phis[NE * NL];

    const int tid = threadIdx.x;
    const size_t rowBase = (size_t)blockIdx.x * 64;

    // Stage constants
    for (int i = tid; i < NE * NL * NO; i += 256) pis[i] = pi[i];
    for (int i = tid; i < NE * NL; i += 256) phis[i] = phi[i];
    if (tid < NL) b2s[tid] = b2[tid];

    // ---- GEMM phase: latent[64,64] = sigmoid(h[64,384] @ W2[384,64] + b2) ----
    const int trow = tid / 16;   // 0..15 -> rows trow*4..+3
    const int tcol = tid % 16;   // 0..15 -> cols tcol*4..+3
    float acc[4][4];
#pragma unroll
    for (int i = 0; i < 4; i++)
#pragma unroll
        for (int j = 0; j < 4; j++) acc[i][j] = 0.0f;

    const int hR = tid / 4;          // 0..63
    const int hC = (tid % 4) * 4;    // 0,4,8,12
    const int wR = tid / 16;         // 0..15
    const int wC = (tid % 16) * 4;   // 0..60

    for (int k0 = 0; k0 < NH; k0 += 16) {
        // h tile: rows rowBase..+63, cols k0..+15, stored transposed
        float4 hv = *(const float4*)(g_h + (rowBase + hR) * NH + k0 + hC);
        hs[(hC + 0) * 64 + hR] = hv.x;
        hs[(hC + 1) * 64 + hR] = hv.y;
        hs[(hC + 2) * 64 + hR] = hv.z;
        hs[(hC + 3) * 64 + hR] = hv.w;
        // W2 tile: rows k0..+15, all 64 cols
        float4 wv = *(const float4*)(W2 + (size_t)(k0 + wR) * NL + wC);
        *(float4*)&w2s[wR * 64 + wC] = wv;
        __syncthreads();

#pragma unroll
        for (int kk = 0; kk < 16; kk++) {
            float4 av = *(const float4*)&hs[kk * 64 + trow * 4];
            float4 bv = *(const float4*)&w2s[kk * 64 + tcol * 4];
            float a[4] = {av.x, av.y, av.z, av.w};
            float b[4] = {bv.x, bv.y, bv.z, bv.w};
#pragma unroll
            for (int i = 0; i < 4; i++)
#pragma unroll
                for (int j = 0; j < 4; j++)
                    acc[i][j] = fmaf(a[i], b[j], acc[i][j]);
        }
        __syncthreads();
    }

    // sigmoid + store latent to smem (padded)
#pragma unroll
    for (int i = 0; i < 4; i++) {
        int r = trow * 4 + i;
#pragma unroll
        for (int j = 0; j < 4; j++) {
            int c = tcol * 4 + j;
            lat[r * 65 + c] = fsigmoid(acc[i][j] + b2s[c]);
        }
    }
    __syncthreads();

    // ---- Tree phase: 4 threads per row, each owns 4 outputs ----
    const int row = tid & 63;
    const int obase = (tid >> 6) * 4;   // 0,4,8,12
    const float* latrow = lat + row * 65;

    float accO[4] = {0.0f, 0.0f, 0.0f, 0.0f};

#pragma unroll 1
    for (int e = 0; e < NE; e++) {
        const int* phie = phis + e * NL;
        float mu[64];
        mu[0] = 1.0f;
        // level doubling: node = 2^lev + j ; children 2j (d) and 2j+1 (1-d)
#pragma unroll
        for (int lev = 0; lev < 6; lev++) {
#pragma unroll
            for (int j = (1 << lev) - 1; j >= 0; j--) {
                int node = (1 << lev) + j;
                float d = latrow[phie[node]];
                float p = mu[j];
                mu[2 * j + 1] = p * (1.0f - d);
                mu[2 * j]     = p * d;
            }
        }
        const float* pie = pis + e * NL * NO;
#pragma unroll
        for (int l = 0; l < NL; l++) {
            float m = mu[l];
            const float* pirow = pie + l * NO + obase;
#pragma unroll
            for (int o = 0; o < 4; o++)
                accO[o] = fmaf(m, pirow[o], accO[o]);
        }
    }

    float* orow = out + (rowBase + row) * NO + obase;
#pragma unroll
    for (int o = 0; o < 4; o++)
        orow[o] = accO[o] * (1.0f / NE);
}

// ---------------------------------------------------------------------------
extern "C" void kernel_launch(void* const* d_in, const int* in_sizes, int n_in,
                              void* d_out, int out_size) {
    const float* X   = (const float*)d_in[0];
    const float* W1  = (const float*)d_in[1];
    const float* b1  = (const float*)d_in[2];
    const float* W2  = (const float*)d_in[3];
    const float* b2  = (const float*)d_in[4];
    const int*   phi = (const int*)d_in[5];
    const float* pi  = (const float*)d_in[6];
    float* out = (float*)d_out;

    const int N = in_sizes[0] / NF;   // 131072

    dim3 g1(NH / BN, N / BM);         // (3, 1024)
    gemm1_sigmoid<<<g1, 256>>>(X, W1, b1);
    fused2<<<N / 64, 256>>>(W2, b2, phi, pi, out);
}

// round 7
// speedup vs baseline: 1.5795x; 1.5795x over previous
#include <cuda_runtime.h>
#include <cuda_bf16.h>
#include <cstdint>

// Shapes: X[131072,256], W1[256,384], b1[384], W2[384,64], b2[64],
//         phi[5,64] i32, pi[5,64,16], out[131072,16]
#define NF  256
#define NH  384
#define NL  64
#define NO  16
#define NE  5

#define KS  136          // padded smem k-stride in bf16 elems (272 B rows)

// ---------------------------------------------------------------------------
// Weight tables: bf16 hi/lo, transposed to [n][k] tiles (static device mem)
//   gW1T[s]: [nc=3][kc=2][n=128][k=128]   (B operand for GEMM1)
//   gW2T[s]: [kc=3][n=64][k=128]          (B operand for GEMM2)
// ---------------------------------------------------------------------------
__device__ __nv_bfloat16 gW1T[2][98304];
__device__ __nv_bfloat16 gW2T[2][24576];

__global__ void conv_w(const float* __restrict__ W1, const float* __restrict__ W2) {
    int idx = blockIdx.x * 256 + threadIdx.x;
    if (idx < 98304) {
        int k  = idx & 127;
        int n  = (idx >> 7) & 127;
        int kc = (idx >> 14) & 1;
        int nc = idx >> 15;                       // 0..2
        float v = W1[(size_t)(kc * 128 + k) * NH + nc * 128 + n];
        __nv_bfloat16 hi = __float2bfloat16(v);
        __nv_bfloat16 lo = __float2bfloat16(v - __bfloat162float(hi));
        gW1T[0][idx] = hi;
        gW1T[1][idx] = lo;
    }
    if (idx < 24576) {
        int k  = idx & 127;
        int n  = (idx >> 7) & 63;
        int kc = idx >> 13;                       // 0..2
        float v = W2[(size_t)(kc * 128 + k) * NL + n];
        __nv_bfloat16 hi = __float2bfloat16(v);
        __nv_bfloat16 lo = __float2bfloat16(v - __bfloat162float(hi));
        gW2T[0][idx] = hi;
        gW2T[1][idx] = lo;
    }
}

// ---------------------------------------------------------------------------
// PTX helpers: ldmatrix + mma.sync (sm_80 features, valid on plain sm_103)
// ---------------------------------------------------------------------------
__device__ __forceinline__ uint32_t smem_u32(const void* p) {
    uint32_t a;
    asm("{ .reg .u64 t; cvta.to.shared.u64 t, %1; cvt.u32.u64 %0, t; }"
        : "=r"(a) : "l"(p));
    return a;
}

#define LDM_X4(r, addr) \
    asm volatile("ldmatrix.sync.aligned.m8n8.x4.shared.b16 {%0,%1,%2,%3}, [%4];" \
        : "=r"((r)[0]), "=r"((r)[1]), "=r"((r)[2]), "=r"((r)[3]) : "r"(addr))

__device__ __forceinline__ void mma_bf16(float* c, const uint32_t* a, const uint32_t* b) {
    asm volatile("mma.sync.aligned.m16n8k16.row.col.f32.bf16.bf16.f32 "
        "{%0,%1,%2,%3}, {%4,%5,%6,%7}, {%8,%9}, {%0,%1,%2,%3};"
        : "+f"(c[0]), "+f"(c[1]), "+f"(c[2]), "+f"(c[3])
        : "r"(a[0]), "r"(a[1]), "r"(a[2]), "r"(a[3]), "r"(b[0]), "r"(b[1]));
}

__device__ __forceinline__ float fsigmoid(float v) {
    return 1.0f / (1.0f + __expf(-v));
}

// ---------------------------------------------------------------------------
// SMEM layout (bytes):
//   SM_X   = 0       : X tile hi  [128][KS] bf16  (34816)
//   SM_XLO = 34816   : X tile lo
//   SM_W1  = 69632   : W1 tile hi [128n][KS]  -- reused as Hs hi, then lat
//   SM_W1LO= 104448  : W1 tile lo -- reused as Hs lo
//   SM_W2  = 139264  : W2 tile hi [64n][KS]   (17408)
//   SM_W2LO= 156672  : W2 tile lo
//   SM_PI  = 174080  : pi (20480)
//   SM_PHI = 194560  : phi (1280)
//   SM_B1  = 195840  : b1 (1536)
//   SM_B2  = 197376  : b2 (256)
// ---------------------------------------------------------------------------
#define SM_X    0
#define SM_XLO  34816
#define SM_W1   69632
#define SM_W1LO 104448
#define SM_LAT  69632
#define SM_W2   139264
#define SM_W2LO 156672
#define SM_PI   174080
#define SM_PHI  194560
#define SM_B1   195840
#define SM_B2   197376
#define SMEM_TOTAL 197632

__global__ __launch_bounds__(256, 1)
void fused_all(const float* __restrict__ X, const float* __restrict__ b1,
               const float* __restrict__ b2, const int* __restrict__ phi,
               const float* __restrict__ pi, float* __restrict__ out) {
    extern __shared__ char smem[];
    const uint32_t sb = smem_u32(smem);
    const int tid = threadIdx.x;
    const int wid = tid >> 5;
    const int lane = tid & 31;
    const int g = lane >> 2;        // 0..7
    const int tg = lane & 3;        // 0..3
    const size_t rowBase = (size_t)blockIdx.x * 128;

    // ldmatrix per-lane row selectors
    const int a_dr = lane & 15;                         // row offset
    const int a_dc = (lane >> 4) * 8;                   // col offset
    const int b_dn = (lane & 7) + (lane >> 4) * 8;      // n offset
    const int b_dk = ((lane >> 3) & 1) * 8;             // k offset

    // GEMM1 warp tile: 32 rows x 64 cols
    const int wm = (wid & 3) * 32;
    const int wn = (wid >> 2) * 64;
    // GEMM2 warp tile: 16 rows x 64 cols
    const int wm2 = wid * 16;

    // ---- stage constants (strided loops: counts exceed blockDim!) ----
    {
        float4* pis4 = (float4*)(smem + SM_PI);
        const float4* pi4 = (const float4*)pi;
#pragma unroll
        for (int i = 0; i < 5; i++) pis4[tid + i * 256] = pi4[tid + i * 256];
        int* phis = (int*)(smem + SM_PHI);
        for (int i = tid; i < NE * NL; i += 256) phis[i] = phi[i];
        float* b1s = (float*)(smem + SM_B1);
        for (int i = tid; i < NH; i += 256) b1s[i] = b1[i];
        float* b2s = (float*)(smem + SM_B2);
        if (tid < NL) b2s[tid] = b2[tid];
    }

    const float* b1s = (const float*)(smem + SM_B1);
    const float* b2s = (const float*)(smem + SM_B2);

    float acc2[8][4];
#pragma unroll
    for (int n = 0; n < 8; n++)
#pragma unroll
        for (int r = 0; r < 4; r++) acc2[n][r] = 0.0f;

    // X staging indices: thread -> (row, col-half)
    const int xr = tid >> 1;
    const int xc = (tid & 1) * 64;

#pragma unroll 1
    for (int nc = 0; nc < 3; nc++) {
        float acc1[2][8][4];
#pragma unroll
        for (int m = 0; m < 2; m++)
#pragma unroll
            for (int n = 0; n < 8; n++)
#pragma unroll
                for (int r = 0; r < 4; r++) acc1[m][n][r] = 0.0f;

#pragma unroll 1
        for (int kc = 0; kc < 2; kc++) {
            __syncthreads();   // prior reads of Xs/W1s (and Hs) complete

            // ---- stage X chunk [128][128] fp32 -> bf16 hi/lo ----
            const float* Xp = X + (rowBase + xr) * NF + kc * 128 + xc;
            char* xhi = smem + SM_X   + xr * (KS * 2) + xc * 2;
            char* xlo = smem + SM_XLO + xr * (KS * 2) + xc * 2;
#pragma unroll
            for (int i = 0; i < 16; i++) {
                float4 v = *(const float4*)(Xp + i * 4);
                __nv_bfloat162 h01 = __float22bfloat162_rn(make_float2(v.x, v.y));
                __nv_bfloat162 h23 = __float22bfloat162_rn(make_float2(v.z, v.w));
                __nv_bfloat162 l01 = __float22bfloat162_rn(make_float2(
                    v.x - __bfloat162float(h01.x), v.y - __bfloat162float(h01.y)));
                __nv_bfloat162 l23 = __float22bfloat162_rn(make_float2(
                    v.z - __bfloat162float(h23.x), v.w - __bfloat162float(h23.y)));
                *(uint32_t*)(xhi + i * 8)     = *(uint32_t*)&h01;
                *(uint32_t*)(xhi + i * 8 + 4) = *(uint32_t*)&h23;
                *(uint32_t*)(xlo + i * 8)     = *(uint32_t*)&l01;
                *(uint32_t*)(xlo + i * 8 + 4) = *(uint32_t*)&l23;
            }

            // ---- stage W1 tiles (straight copy from pre-split tables) ----
#pragma unroll
            for (int s = 0; s < 2; s++) {
                const uint4* src = (const uint4*)(&gW1T[s][(nc * 2 + kc) * 16384]);
                char* dst = smem + (s ? SM_W1LO : SM_W1);
#pragma unroll
                for (int i = 0; i < 8; i++) {
                    int j = tid + i * 256;
                    int n = j >> 4, kv = j & 15;
                    *(uint4*)(dst + n * (KS * 2) + kv * 16) = src[j];
                }
            }
            __syncthreads();

            // ---- GEMM1 mma: 3 passes (hi*hi, hi*lo, lo*hi) ----
#pragma unroll
            for (int pass = 0; pass < 3; pass++) {
                uint32_t Ab = sb + (pass == 2 ? SM_XLO : SM_X)
                            + ((wm + a_dr) * KS + a_dc) * 2;
                uint32_t Bb = sb + (pass == 1 ? SM_W1LO : SM_W1)
                            + ((wn + b_dn) * KS + b_dk) * 2;
#pragma unroll
                for (int k16 = 0; k16 < 8; k16++) {
                    uint32_t a[2][4];
                    LDM_X4(a[0], Ab + k16 * 32);
                    LDM_X4(a[1], Ab + k16 * 32 + 16 * KS * 2);
                    uint32_t bq[4][4];
#pragma unroll
                    for (int p = 0; p < 4; p++)
                        LDM_X4(bq[p], Bb + k16 * 32 + p * 16 * KS * 2);
#pragma unroll
                    for (int m = 0; m < 2; m++)
#pragma unroll
                        for (int n = 0; n < 8; n++)
                            mma_bf16(acc1[m][n], a[m], &bq[n >> 1][(n & 1) * 2]);
                }
            }
        }
        __syncthreads();   // all GEMM1 reads of W1s done -> safe to overwrite with Hs

        // ---- epilogue1: h = sigmoid(acc1 + b1) -> Hs hi/lo (W1s region) ----
#pragma unroll
        for (int m = 0; m < 2; m++) {
            int row0 = wm + m * 16 + g;
#pragma unroll
            for (int n = 0; n < 8; n++) {
                int col = wn + n * 8 + 2 * tg;               // k index for GEMM2
                float bb0 = b1s[nc * 128 + col];
                float bb1 = b1s[nc * 128 + col + 1];
                float f0 = fsigmoid(acc1[m][n][0] + bb0);
                float f1 = fsigmoid(acc1[m][n][1] + bb1);
                float f2 = fsigmoid(acc1[m][n][2] + bb0);
                float f3 = fsigmoid(acc1[m][n][3] + bb1);
                __nv_bfloat162 h01 = __float22bfloat162_rn(make_float2(f0, f1));
                __nv_bfloat162 h23 = __float22bfloat162_rn(make_float2(f2, f3));
                __nv_bfloat162 l01 = __float22bfloat162_rn(make_float2(
                    f0 - __bfloat162float(h01.x), f1 - __bfloat162float(h01.y)));
                __nv_bfloat162 l23 = __float22bfloat162_rn(make_float2(
                    f2 - __bfloat162float(h23.x), f3 - __bfloat162float(h23.y)));
                *(uint32_t*)(smem + SM_W1   + (row0 * KS + col) * 2)       = *(uint32_t*)&h01;
                *(uint32_t*)(smem + SM_W1   + ((row0 + 8) * KS + col) * 2) = *(uint32_t*)&h23;
                *(uint32_t*)(smem + SM_W1LO + (row0 * KS + col) * 2)       = *(uint32_t*)&l01;
                *(uint32_t*)(smem + SM_W1LO + ((row0 + 8) * KS + col) * 2) = *(uint32_t*)&l23;
            }
        }

        // ---- stage W2 chunk ----
#pragma unroll
        for (int s = 0; s < 2; s++) {
            const uint4* src = (const uint4*)(&gW2T[s][nc * 8192]);
            char* dst = smem + (s ? SM_W2LO : SM_W2);
#pragma unroll
            for (int i = 0; i < 4; i++) {
                int j = tid + i * 256;
                int n = j >> 4, kv = j & 15;
                *(uint4*)(dst + n * (KS * 2) + kv * 16) = src[j];
            }
        }
        __syncthreads();

        // ---- GEMM2 mma: latacc += Hc @ W2c, 3 passes ----
#pragma unroll
        for (int pass = 0; pass < 3; pass++) {
            uint32_t Ab = sb + (pass == 2 ? SM_W1LO : SM_W1)
                        + ((wm2 + a_dr) * KS + a_dc) * 2;
            uint32_t Bb = sb + (pass == 1 ? SM_W2LO : SM_W2)
                        + (b_dn * KS + b_dk) * 2;
#pragma unroll
            for (int k16 = 0; k16 < 8; k16++) {
                uint32_t a[4];
                LDM_X4(a, Ab + k16 * 32);
                uint32_t bq[4][4];
#pragma unroll
                for (int p = 0; p < 4; p++)
                    LDM_X4(bq[p], Bb + k16 * 32 + p * 16 * KS * 2);
#pragma unroll
                for (int n = 0; n < 8; n++)
                    mma_bf16(acc2[n], a, &bq[n >> 1][(n & 1) * 2]);
            }
        }
    }
    __syncthreads();   // GEMM2 reads of Hs done -> lat can overlay region

    // ---- latent = sigmoid(acc2 + b2) -> lat smem ----
    float* lat = (float*)(smem + SM_LAT);
#pragma unroll
    for (int n = 0; n < 8; n++) {
        int c0 = n * 8 + 2 * tg;
        lat[(wm2 + g) * 65 + c0]         = fsigmoid(acc2[n][0] + b2s[c0]);
        lat[(wm2 + g) * 65 + c0 + 1]     = fsigmoid(acc2[n][1] + b2s[c0 + 1]);
        lat[(wm2 + g + 8) * 65 + c0]     = fsigmoid(acc2[n][2] + b2s[c0]);
        lat[(wm2 + g + 8) * 65 + c0 + 1] = fsigmoid(acc2[n][3] + b2s[c0 + 1]);
    }
    __syncthreads();

    // ---- tree + pi contraction ----
    {
        const int row = tid & 127;
        const int obase = (tid >> 7) * 8;
        const float* latrow = lat + row * 65;
        const int* phis = (const int*)(smem + SM_PHI);
        const float* pis = (const float*)(smem + SM_PI);
        float accO[8];
#pragma unroll
        for (int o = 0; o < 8; o++) accO[o] = 0.0f;

#pragma unroll 1
        for (int e = 0; e < NE; e++) {
            const int* phie = phis + e * NL;
            float mu[64];
            mu[0] = 1.0f;
#pragma unroll
            for (int lev = 0; lev < 6; lev++) {
#pragma unroll
                for (int j = (1 << lev) - 1; j >= 0; j--) {
                    int node = (1 << lev) + j;
                    float d = latrow[phie[node]];
                    float p = mu[j];
                    mu[2 * j + 1] = p * (1.0f - d);
                    mu[2 * j]     = p * d;
                }
            }
            const float* pie = pis + e * NL * NO;
#pragma unroll
            for (int l = 0; l < NL; l++) {
                float m = mu[l];
                const float* pr = pie + l * NO + obase;
#pragma unroll
                for (int o = 0; o < 8; o++)
                    accO[o] = fmaf(m, pr[o], accO[o]);
            }
        }
        float4 o0, o1;
        o0.x = accO[0] * 0.2f; o0.y = accO[1] * 0.2f;
        o0.z = accO[2] * 0.2f; o0.w = accO[3] * 0.2f;
        o1.x = accO[4] * 0.2f; o1.y = accO[5] * 0.2f;
        o1.z = accO[6] * 0.2f; o1.w = accO[7] * 0.2f;
        float* op = out + (rowBase + row) * NO + obase;
        *(float4*)op       = o0;
        *(float4*)(op + 4) = o1;
    }
}

// ---------------------------------------------------------------------------
extern "C" void kernel_launch(void* const* d_in, const int* in_sizes, int n_in,
                              void* d_out, int out_size) {
    const float* X   = (const float*)d_in[0];
    const float* W1  = (const float*)d_in[1];
    const float* b1  = (const float*)d_in[2];
    const float* W2  = (const float*)d_in[3];
    const float* b2  = (const float*)d_in[4];
    const int*   phi = (const int*)d_in[5];
    const float* pi  = (const float*)d_in[6];
    float* out = (float*)d_out;

    const int N = in_sizes[0] / NF;   // 131072

    cudaFuncSetAttribute(fused_all, cudaFuncAttributeMaxDynamicSharedMemorySize,
                         SMEM_TOTAL);

    conv_w<<<384, 256>>>(W1, W2);
    fused_all<<<N / 128, 256, SMEM_TOTAL>>>(X, b1, b2, phi, pi, out);
}